// round 15
// baseline (speedup 1.0000x reference)
#include <cuda_runtime.h>
#include <cstdint>

#define NU 100000
#define NI 50000
#define NE 1000000
#define EMB 64
#define DV 16            // float4 chunks per row

#define TILE 1024
#define NBU ((NU + TILE - 1) / TILE)   // 98
#define NBI ((NI + TILE - 1) / TILE)   // 49

// ---------------------------------------------------------------------------
// __device__ scratch (zero-initialized at module load; no allocations)
// ---------------------------------------------------------------------------
__device__ float g_u1[NU * EMB];
__device__ float g_i1[NI * EMB];
__device__ int   g_degU[NU];        // invariant: zero at kernel_launch entry
__device__ int   g_degI[NI];        // (restored by scan_fused each call)
__device__ int   g_offU[NU + 1];
__device__ int   g_offI[NI + 1];
__device__ float g_invU[NU];
__device__ float g_invI[NI];
__device__ int   g_csrU[NE];
__device__ int   g_csrI[NE];
__device__ int   g_rankU[NE];
__device__ int   g_rankI[NE];
__device__ int   g_tsU[NBU];        // published tile totals (+1 flag encoding)
__device__ int   g_tsI[NBI];        // zeroed by degree_kernel each call

// ---------------------------------------------------------------------------
// (1) degrees + per-edge ranks; also re-zeroes the lookback flags
// ---------------------------------------------------------------------------
__global__ void degree_kernel(const int4* __restrict__ es4,
                              const int4* __restrict__ ed4) {
    int t = blockIdx.x * blockDim.x + threadIdx.x;
    if (t < NBU) g_tsU[t] = 0;
    if (t < NBI) g_tsI[t] = 0;
    if (t < NE / 4) {
        int4 s = __ldg(&es4[t]);
        int4 d = __ldg(&ed4[t]);
        int4 ru, ri;
        ru.x = atomicAdd(&g_degU[s.x], 1);
        ru.y = atomicAdd(&g_degU[s.y], 1);
        ru.z = atomicAdd(&g_degU[s.z], 1);
        ru.w = atomicAdd(&g_degU[s.w], 1);
        ri.x = atomicAdd(&g_degI[d.x], 1);
        ri.y = atomicAdd(&g_degI[d.y], 1);
        ri.z = atomicAdd(&g_degI[d.z], 1);
        ri.w = atomicAdd(&g_degI[d.w], 1);
        reinterpret_cast<int4*>(g_rankU)[t] = ru;
        reinterpret_cast<int4*>(g_rankI)[t] = ri;
    }
}

// ---------------------------------------------------------------------------
// (2) single-pass exclusive scan (decoupled lookback, parallel polling).
//     Block = one 1024-elem tile. Publishes its tile total immediately
//     (value+1, 0 == not ready); each block's threads t<tileIdx poll one
//     predecessor each, tree-reduce to get the base. All 147 blocks fit in
//     one wave -> progress guaranteed. Writes off/inv, re-zeroes deg.
// ---------------------------------------------------------------------------
__global__ void __launch_bounds__(256)
scan_fused() {
    __shared__ int ssum[256];
    __shared__ int sbase[256];
    int b = blockIdx.x;
    bool isU = (b < NBU);
    int tileIdx = isU ? b : b - NBU;
    int nTiles  = isU ? NBU : NBI;
    int n       = isU ? NU : NI;
    int* deg   = isU ? g_degU : g_degI;
    int* off   = isU ? g_offU : g_offI;
    float* inv = isU ? g_invU : g_invI;
    int* ts    = isU ? g_tsU : g_tsI;

    int t = threadIdx.x;
    int i4 = tileIdx * (TILE / 4) + t;
    int e0 = i4 * 4;
    int4 v = make_int4(0, 0, 0, 0);
    bool act = (e0 < n);
    if (act) v = reinterpret_cast<const int4*>(deg)[i4];
    int s = v.x + v.y + v.z + v.w;

    // Hillis-Steele inclusive scan over the 256 thread sums
    ssum[t] = s;
    __syncthreads();
    for (int st = 1; st < 256; st <<= 1) {
        int o = (t >= st) ? ssum[t - st] : 0;
        __syncthreads();
        ssum[t] += o;
        __syncthreads();
    }
    int tileTotal = ssum[255];

    // publish own total ASAP (flag-encoded +1)
    if (t == 0) atomicExch(&ts[tileIdx], tileTotal + 1);

    // gather predecessors' totals in parallel (one per thread), reduce
    int pv = 0;
    if (t < tileIdx) {                        // tileIdx <= 97 < 256
        int p;
        do { p = atomicAdd(&ts[t], 0); } while (p == 0);
        pv = p - 1;
    }
    sbase[t] = pv;
    __syncthreads();
    for (int st = 128; st > 0; st >>= 1) {
        if (t < st) sbase[t] += sbase[t + st];
        __syncthreads();
    }
    int base = sbase[0];

    int pfx = base + ssum[t] - s;
    if (act) {
        off[e0 + 0] = pfx;  inv[e0 + 0] = v.x ? 1.0f / v.x : 0.f;  pfx += v.x;
        off[e0 + 1] = pfx;  inv[e0 + 1] = v.y ? 1.0f / v.y : 0.f;  pfx += v.y;
        off[e0 + 2] = pfx;  inv[e0 + 2] = v.z ? 1.0f / v.z : 0.f;  pfx += v.z;
        off[e0 + 3] = pfx;  inv[e0 + 3] = v.w ? 1.0f / v.w : 0.f;
        reinterpret_cast<int4*>(deg)[i4] = make_int4(0, 0, 0, 0);
    }
    if (tileIdx == nTiles - 1 && t == 255)
        off[n] = base + tileTotal;
}

// ---------------------------------------------------------------------------
// (3) build CSR — atomic-free: slot = off[node] + precomputed rank
// ---------------------------------------------------------------------------
__global__ void build_csr(const int4* __restrict__ es4,
                          const int4* __restrict__ ed4) {
    int t = blockIdx.x * blockDim.x + threadIdx.x;
    if (t < NE / 4) {
        int4 s  = __ldg(&es4[t]);
        int4 d  = __ldg(&ed4[t]);
        int4 ru = reinterpret_cast<const int4*>(g_rankU)[t];
        int4 ri = reinterpret_cast<const int4*>(g_rankI)[t];
        g_csrI[__ldg(&g_offI[d.x]) + ri.x] = s.x;
        g_csrI[__ldg(&g_offI[d.y]) + ri.y] = s.y;
        g_csrI[__ldg(&g_offI[d.z]) + ri.z] = s.z;
        g_csrI[__ldg(&g_offI[d.w]) + ri.w] = s.w;
        g_csrU[__ldg(&g_offU[s.x]) + ru.x] = d.x;
        g_csrU[__ldg(&g_offU[s.y]) + ru.y] = d.y;
        g_csrU[__ldg(&g_offU[s.z]) + ru.z] = d.z;
        g_csrU[__ldg(&g_offU[s.w]) + ru.w] = d.w;
    }
}

// ---------------------------------------------------------------------------
// (4)/(5) fused round — ROW-PAIR shape (measured ~49µs in R11, unchanged):
//   each warp covers rows 2w and 2w+1; half h owns row 2w+h, unroll-8.
// ---------------------------------------------------------------------------
__global__ void __launch_bounds__(256)
round_kernel(const float4* __restrict__ uin,
             const float4* __restrict__ iin,
             const float*  __restrict__ usw,
             const float*  __restrict__ isw,
             float4* __restrict__ uout,
             float4* __restrict__ iout) {
    int warpId = (blockIdx.x * blockDim.x + threadIdx.x) >> 5;
    int lane   = threadIdx.x & 31;
    int c      = lane & 15;
    int h      = lane >> 4;
    int row    = warpId * 2 + h;
    if (row >= NI + NU) return;

    const float4* src;
    const int*    adj;
    int off, end, outIdx;
    float inv, sw;
    float4 x;
    float4* outp;

    if (row < NI) {
        int r = row;
        off = g_offI[r]; end = g_offI[r + 1];
        src = uin; adj = g_csrI;
        inv = g_invI[r]; sw = isw[r];
        outIdx = r * DV + c;
        x = iin[outIdx];
        outp = iout;
    } else {
        int r = row - NI;
        off = g_offU[r]; end = g_offU[r + 1];
        src = iin; adj = g_csrU;
        inv = g_invU[r]; sw = usw[r];
        outIdx = r * DV + c;
        x = uin[outIdx];
        outp = uout;
    }

    float4 acc = make_float4(0.f, 0.f, 0.f, 0.f);
    int k = off;
    for (; k + 8 <= end; k += 8) {
        int s0 = __ldg(&adj[k    ]);
        int s1 = __ldg(&adj[k + 1]);
        int s2 = __ldg(&adj[k + 2]);
        int s3 = __ldg(&adj[k + 3]);
        int s4 = __ldg(&adj[k + 4]);
        int s5 = __ldg(&adj[k + 5]);
        int s6 = __ldg(&adj[k + 6]);
        int s7 = __ldg(&adj[k + 7]);
        float4 a0 = src[s0 * DV + c];
        float4 a1 = src[s1 * DV + c];
        float4 a2 = src[s2 * DV + c];
        float4 a3 = src[s3 * DV + c];
        float4 a4 = src[s4 * DV + c];
        float4 a5 = src[s5 * DV + c];
        float4 a6 = src[s6 * DV + c];
        float4 a7 = src[s7 * DV + c];
        acc.x += ((a0.x + a1.x) + (a2.x + a3.x)) + ((a4.x + a5.x) + (a6.x + a7.x));
        acc.y += ((a0.y + a1.y) + (a2.y + a3.y)) + ((a4.y + a5.y) + (a6.y + a7.y));
        acc.z += ((a0.z + a1.z) + (a2.z + a3.z)) + ((a4.z + a5.z) + (a6.z + a7.z));
        acc.w += ((a0.w + a1.w) + (a2.w + a3.w)) + ((a4.w + a5.w) + (a6.w + a7.w));
    }
    for (; k < end; k++) {
        float4 a = src[__ldg(&adj[k]) * DV + c];
        acc.x += a.x; acc.y += a.y; acc.z += a.z; acc.w += a.w;
    }

    float4 r;
    r.x = acc.x * inv + x.x * sw;
    r.y = acc.y * inv + x.y * sw;
    r.z = acc.z * inv + x.z * sw;
    r.w = acc.w * inv + x.w * sw;
    outp[outIdx] = r;
}

// ---------------------------------------------------------------------------
// Launch: degree(1), scan(2), build(3), round1(4)<-profiled, round2(5)
// ---------------------------------------------------------------------------
extern "C" void kernel_launch(void* const* d_in, const int* in_sizes, int n_in,
                              void* d_out, int out_size) {
    const float* user_emb = (const float*)d_in[0];
    const float* item_emb = (const float*)d_in[1];
    const float* u_sw     = (const float*)d_in[2];
    const float* i_sw     = (const float*)d_in[3];
    const int*   e_src    = (const int*)d_in[4];
    const int*   e_dst    = (const int*)d_in[5];

    float* out_u = (float*)d_out;
    float* out_i = (float*)d_out + (int64_t)NU * EMB;

    void* p;
    cudaGetSymbolAddress(&p, g_u1); float4* u1p = (float4*)p;
    cudaGetSymbolAddress(&p, g_i1); float4* i1p = (float4*)p;

    const int TPB = 256;
    const int eThreads = NE / 4;

    degree_kernel<<<(eThreads + TPB - 1) / TPB, TPB>>>(
        (const int4*)e_src, (const int4*)e_dst);

    scan_fused<<<NBU + NBI, 256>>>();

    build_csr<<<(eThreads + TPB - 1) / TPB, TPB>>>(
        (const int4*)e_src, (const int4*)e_dst);

    int warps = (NI + NU) / 2;                       // 75000
    int rblocks = (warps * 32 + TPB - 1) / TPB;      // 9375

    round_kernel<<<rblocks, TPB>>>((const float4*)user_emb,
                                   (const float4*)item_emb,
                                   u_sw, i_sw, u1p, i1p);

    round_kernel<<<rblocks, TPB>>>((const float4*)u1p,
                                   (const float4*)i1p,
                                   u_sw, i_sw,
                                   (float4*)out_u, (float4*)out_i);
}